// round 6
// baseline (speedup 1.0000x reference)
#include <cuda_runtime.h>
#include <cuda_fp16.h>

#define U_N   100000
#define I_N   50000
#define NUI   150000
#define NALL  (NUI + I_N)
#define KDIM  64
#define E_II  1600000
#define E_UI  4800000
#define EPS_F 1e-12f

#define CHUNK    1024
#define NCH_UI   ((NUI + CHUNK - 1) / CHUNK)   // 147
#define NCH_II   ((I_N + CHUNK - 1) / CHUNK)   // 49
#define NCH_TOT  (NCH_UI + NCH_II)             // 196

// ---------------- static device scratch (allocation-free) ----------------
__device__ int2  g_ui_csr[E_UI];       // packed (src, weight-bits)
__device__ int2  g_ii_csr[E_II];
__device__ int   g_ui_off[NUI + 1];
__device__ int   g_ui_cur[NUI];
__device__ int   g_ii_off[I_N + 1];
__device__ int   g_ii_cur[I_N];
__device__ int   g_chunksum[NCH_TOT];
__device__ int   g_chunkoff[NCH_TOT];

// fp16 propagation buffers; float4-typed for 16B alignment. Row = 128B = 8 float4.
__device__ float4 g_eh0[NUI * 8];
__device__ float4 g_eh1[NUI * 8];
__device__ float4 g_gh0[I_N * 8];
__device__ float4 g_gh1[I_N * 8];

// ---------------- CSR build ----------------
__global__ void k_zero() {
    int stride = gridDim.x * blockDim.x;
    for (int i = blockIdx.x * blockDim.x + threadIdx.x; i < NUI; i += stride) {
        g_ui_cur[i] = 0;
        if (i < I_N) g_ii_cur[i] = 0;
    }
}

__global__ void k_count(const int* __restrict__ ui_dst, const int* __restrict__ ii_dst) {
    int stride = gridDim.x * blockDim.x;
    for (int e = blockIdx.x * blockDim.x + threadIdx.x; e < E_UI; e += stride) {
        atomicAdd(&g_ui_cur[ui_dst[e]], 1);
        if (e < E_II) atomicAdd(&g_ii_cur[ii_dst[e]], 1);
    }
}

__global__ void __launch_bounds__(256) k_scan_partial() {
    int b = blockIdx.x;
    const int* deg;
    int base, n;
    if (b < NCH_UI) { deg = g_ui_cur; base = b * CHUNK; n = NUI; }
    else            { deg = g_ii_cur; base = (b - NCH_UI) * CHUNK; n = I_N; }

    int t = threadIdx.x;
    int i0 = base + t * 4;
    int s = 0;
    #pragma unroll
    for (int k = 0; k < 4; k++) {
        int i = i0 + k;
        if (i < n) s += deg[i];
    }
    #pragma unroll
    for (int o = 16; o; o >>= 1) s += __shfl_xor_sync(0xffffffffu, s, o);
    __shared__ int wsum[8];
    int lane = t & 31, wid = t >> 5;
    if (lane == 0) wsum[wid] = s;
    __syncthreads();
    if (t == 0) {
        int tot = 0;
        #pragma unroll
        for (int w = 0; w < 8; w++) tot += wsum[w];
        g_chunksum[b] = tot;
    }
}

__global__ void k_scan_chunks() {
    __shared__ int sh[NCH_TOT];
    int t = threadIdx.x;
    if (t < NCH_TOT) sh[t] = g_chunksum[t];
    __syncthreads();
    if (t == 0) {
        int run = 0;
        for (int c = 0; c < NCH_UI; c++) { int v = sh[c]; sh[c] = run; run += v; }
        run = 0;
        for (int c = NCH_UI; c < NCH_TOT; c++) { int v = sh[c]; sh[c] = run; run += v; }
        g_ui_off[NUI] = E_UI;
        g_ii_off[I_N] = E_II;
    }
    __syncthreads();
    if (t < NCH_TOT) g_chunkoff[t] = sh[t];
}

__global__ void __launch_bounds__(256) k_scan_final() {
    int b = blockIdx.x;
    int* deg; int* off;
    int base, n;
    if (b < NCH_UI) { deg = g_ui_cur; off = g_ui_off; base = b * CHUNK; n = NUI; }
    else            { deg = g_ii_cur; off = g_ii_off; base = (b - NCH_UI) * CHUNK; n = I_N; }
    int coff = g_chunkoff[b];

    int t = threadIdx.x;
    int lane = t & 31, wid = t >> 5;
    int i0 = base + t * 4;
    int v[4];
    int s = 0;
    #pragma unroll
    for (int k = 0; k < 4; k++) {
        int i = i0 + k;
        v[k] = (i < n) ? deg[i] : 0;
        s += v[k];
    }
    int x = s;
    #pragma unroll
    for (int o = 1; o < 32; o <<= 1) {
        int tmp = __shfl_up_sync(0xffffffffu, x, o);
        if (lane >= o) x += tmp;
    }
    __shared__ int wsum[8];
    if (lane == 31) wsum[wid] = x;
    __syncthreads();
    __shared__ int wexc[8];
    if (t == 0) {
        int run = 0;
        #pragma unroll
        for (int w = 0; w < 8; w++) { int tv = wsum[w]; wexc[w] = run; run += tv; }
    }
    __syncthreads();
    int running = coff + (x - s) + wexc[wid];
    #pragma unroll
    for (int k = 0; k < 4; k++) {
        int i = i0 + k;
        if (i < n) { off[i] = running; deg[i] = running; }
        running += v[k];
    }
}

__global__ void k_fill(const int* __restrict__ ui_src, const int* __restrict__ ui_dst,
                       const float* __restrict__ ui_w,
                       const int* __restrict__ ii_src, const int* __restrict__ ii_dst,
                       const float* __restrict__ ii_w) {
    int stride = gridDim.x * blockDim.x;
    for (int e = blockIdx.x * blockDim.x + threadIdx.x; e < E_UI; e += stride) {
        int d = ui_dst[e];
        int p = atomicAdd(&g_ui_cur[d], 1);
        g_ui_csr[p] = make_int2(ui_src[e], __float_as_int(ui_w[e]));
        if (e < E_II) {
            int d2 = ii_dst[e];
            int p2 = atomicAdd(&g_ii_cur[d2], 1);
            g_ii_csr[p2] = make_int2(ii_src[e], __float_as_int(ii_w[e]));
        }
    }
}

// ---------------- init: eh0 = fp16(ego), gh0 = fp16(Gis) ----------------
__global__ void k_init(const float* __restrict__ Gu, const float* __restrict__ Gi,
                       const float* __restrict__ Gis) {
    const int n1  = NUI * 32;
    const int nGu = U_N * 32;
    const int tot = n1 + I_N * 32;
    __half2* eh0 = (__half2*)g_eh0;
    __half2* gh0 = (__half2*)g_gh0;
    int stride = gridDim.x * blockDim.x;
    for (int i = blockIdx.x * blockDim.x + threadIdx.x; i < tot; i += stride) {
        if (i < n1) {
            float2 v = (i < nGu) ? ((const float2*)Gu)[i] : ((const float2*)Gi)[i - nGu];
            eh0[i] = __float22half2_rn(v);
        } else {
            float2 v = ((const float2*)Gis)[i - n1];
            gh0[i - n1] = __float22half2_rn(v);
        }
    }
}

// ---------------- gather core: 4 edge-slots x 8 lanes, 8-edge unroll --------
__device__ __forceinline__ void gather_row(const int* __restrict__ off,
                                           const int2* __restrict__ csr,
                                           const float4* __restrict__ x,
                                           int row, int slot, int sub,
                                           float a[8]) {
    int beg = off[row], end = off[row + 1];
    #pragma unroll
    for (int k = 0; k < 8; k++) a[k] = 0.f;

    int2 edA = make_int2(0, 0), edB = make_int2(0, 0);
    if (beg + slot < end)     edA = __ldg(&csr[beg + slot]);
    if (beg + 4 + slot < end) edB = __ldg(&csr[beg + 4 + slot]);

    int e = beg;
    for (; e + 8 <= end; e += 8) {
        int iA = e + 8 + slot, iB = e + 12 + slot;
        int2 nA = (iA < end) ? __ldg(&csr[iA]) : make_int2(0, 0);
        int2 nB = (iB < end) ? __ldg(&csr[iB]) : make_int2(0, 0);
        float4 rA = __ldg(&x[(size_t)edA.x * 8 + sub]);
        float4 rB = __ldg(&x[(size_t)edB.x * 8 + sub]);
        float wA = __int_as_float(edA.y);
        float wB = __int_as_float(edB.y);
        const __half2* hA = (const __half2*)&rA;
        const __half2* hB = (const __half2*)&rB;
        #pragma unroll
        for (int k = 0; k < 4; k++) {
            float2 fA = __half22float2(hA[k]);
            float2 fB = __half22float2(hB[k]);
            a[2 * k]     = fmaf(wA, fA.x, a[2 * k]);
            a[2 * k + 1] = fmaf(wA, fA.y, a[2 * k + 1]);
            a[2 * k]     = fmaf(wB, fB.x, a[2 * k]);
            a[2 * k + 1] = fmaf(wB, fB.y, a[2 * k + 1]);
        }
        edA = nA; edB = nB;
    }
    if (e < end) {
        float4 rA = __ldg(&x[(size_t)edA.x * 8 + sub]);
        float wA = __int_as_float(edA.y);
        const __half2* hA = (const __half2*)&rA;
        #pragma unroll
        for (int k = 0; k < 4; k++) {
            float2 fA = __half22float2(hA[k]);
            a[2 * k]     = fmaf(wA, fA.x, a[2 * k]);
            a[2 * k + 1] = fmaf(wA, fA.y, a[2 * k + 1]);
        }
        if (e + 4 < end) {
            float4 rB = __ldg(&x[(size_t)edB.x * 8 + sub]);
            float wB = __int_as_float(edB.y);
            const __half2* hB = (const __half2*)&rB;
            #pragma unroll
            for (int k = 0; k < 4; k++) {
                float2 fB = __half22float2(hB[k]);
                a[2 * k]     = fmaf(wB, fB.x, a[2 * k]);
                a[2 * k + 1] = fmaf(wB, fB.y, a[2 * k + 1]);
            }
        }
    }

    // cross-slot reduce -> all 4 slots hold identical column sums
    #pragma unroll
    for (int k = 0; k < 8; k++) {
        a[k] += __shfl_xor_sync(0xffffffffu, a[k], 8);
        a[k] += __shfl_xor_sync(0xffffffffu, a[k], 16);
    }
}

__device__ __forceinline__ void l2norm_regs(float a[8]) {
    float ssum = 0.f;
    #pragma unroll
    for (int k = 0; k < 8; k++) ssum = fmaf(a[k], a[k], ssum);
    #pragma unroll
    for (int o = 4; o; o >>= 1) ssum += __shfl_xor_sync(0xffffffffu, ssum, o);
    float scale = 1.f / fmaxf(sqrtf(ssum), EPS_F);
    #pragma unroll
    for (int k = 0; k < 8; k++) a[k] *= scale;
}

__device__ __forceinline__ void store_fp16(float4* y, int row, int sub, const float a[8]) {
    __half2 hp[4];
    #pragma unroll
    for (int k = 0; k < 4; k++)
        hp[k] = __float22half2_rn(make_float2(a[2 * k], a[2 * k + 1]));
    y[(size_t)row * 8 + sub] = *(const float4*)hp;
}

// ---------------- fused layer kernels ----------------
// LAYER 1: rows [0,NUI): UI spmm+norm, eh0->eh1, acc = ego + a
//          rows [NUI,NALL): II spmm, gh0->gh1
// LAYER 2: rows [0,NUI): UI spmm+norm, eh1->eh0, acc += a
//          rows [NUI,NALL): II spmm, gh1->gh0
// LAYER 3: rows [0,NUI): UI spmm+norm from eh0; acc=(acc+a)/4; items += l2norm(gh0)
template <int LAYER>
__global__ void __launch_bounds__(256) k_layer(float* acc,
                                               const float* __restrict__ Gu,
                                               const float* __restrict__ Gi) {
    int row = blockIdx.x * 8 + (threadIdx.x >> 5);
    int lane = threadIdx.x & 31;
    int slot = lane >> 3;
    int sub  = lane & 7;

    float a[8];

    if (LAYER <= 2 && row >= NUI) {
        // ---- II part ----
        int r = row - NUI;
        if (r >= I_N) return;
        const float4* x = (LAYER == 1) ? g_gh0 : g_gh1;
        float4*       y = (LAYER == 1) ? g_gh1 : g_gh0;
        gather_row(g_ii_off, g_ii_csr, x, r, slot, sub, a);
        if (slot == 0) store_fp16(y, r, sub, a);
        return;
    }
    if (row >= NUI) return;

    // ---- UI part ----
    const float4* x = (LAYER == 2) ? g_eh1 : g_eh0;
    gather_row(g_ui_off, g_ui_csr, x, row, slot, sub, a);
    l2norm_regs(a);

    if (LAYER == 1 && slot == 0) store_fp16(g_eh1, row, sub, a);
    if (LAYER == 2 && slot == 0) store_fp16(g_eh0, row, sub, a);

    if (slot < 2) {
        float4* a4 = (float4*)acc;
        size_t p = (size_t)row * 16 + 2 * sub + slot;
        float4 o;
        if (LAYER == 1) {
            o = (row < U_N) ? ((const float4*)Gu)[p]
                            : ((const float4*)Gi)[(size_t)(row - U_N) * 16 + 2 * sub + slot];
        } else {
            o = a4[p];
        }
        o.x += a[4 * slot + 0];
        o.y += a[4 * slot + 1];
        o.z += a[4 * slot + 2];
        o.w += a[4 * slot + 3];
        if (LAYER == 3) {
            o.x *= 0.25f; o.y *= 0.25f; o.z *= 0.25f; o.w *= 0.25f;
            if (row >= U_N) {
                float2 gp = ((const float2*)g_gh0)[(size_t)(row - U_N) * 16 + 2 * sub + slot];
                const __half2* gh = (const __half2*)&gp;
                float2 f0 = __half22float2(gh[0]);
                float2 f1 = __half22float2(gh[1]);
                float ssum = f0.x * f0.x + f0.y * f0.y + f1.x * f1.x + f1.y * f1.y;
                #pragma unroll
                for (int o2 = 8; o2; o2 >>= 1)
                    ssum += __shfl_xor_sync(0xffffffffu, ssum, o2);
                float sc = 1.f / fmaxf(sqrtf(ssum), EPS_F);
                o.x = fmaf(f0.x, sc, o.x);
                o.y = fmaf(f0.y, sc, o.y);
                o.z = fmaf(f1.x, sc, o.z);
                o.w = fmaf(f1.y, sc, o.w);
            }
        }
        a4[p] = o;
    }
}

// ---------------- launch ----------------
extern "C" void kernel_launch(void* const* d_in, const int* in_sizes, int n_in,
                              void* d_out, int out_size) {
    const float* Gu     = (const float*)d_in[0];
    const float* Gi     = (const float*)d_in[1];
    const float* Gis    = (const float*)d_in[2];
    const float* ii_w   = (const float*)d_in[3];
    const float* ui_w   = (const float*)d_in[4];
    const int*   ii_src = (const int*)d_in[5];
    const int*   ii_dst = (const int*)d_in[6];
    const int*   ui_src = (const int*)d_in[7];
    const int*   ui_dst = (const int*)d_in[8];
    float* out = (float*)d_out;

    // CSR build
    k_zero<<<512, 256>>>();
    k_count<<<4096, 256>>>(ui_dst, ii_dst);
    k_scan_partial<<<NCH_TOT, 256>>>();
    k_scan_chunks<<<1, 256>>>();
    k_scan_final<<<NCH_TOT, 256>>>();
    k_fill<<<4096, 256>>>(ui_src, ui_dst, ui_w, ii_src, ii_dst, ii_w);

    // fp16 copies of ego / Gis
    k_init<<<2048, 256>>>(Gu, Gi, Gis);

    int blk_all = (NALL + 7) / 8;   // UI + II fused rows
    int blk_ui  = (NUI + 7) / 8;

    // K1: UI L1 + II L1      K2: UI L2 + II L2      K3: UI L3 + final
    k_layer<1><<<blk_all, 256>>>(out, Gu, Gi);
    k_layer<2><<<blk_all, 256>>>(out, Gu, Gi);
    k_layer<3><<<blk_ui,  256>>>(out, Gu, Gi);
}

// round 7
// speedup vs baseline: 1.2828x; 1.2828x over previous
#include <cuda_runtime.h>
#include <cuda_fp16.h>

#define U_N   100000
#define I_N   50000
#define NUI   150000
#define KDIM  64
#define E_II  1600000
#define E_UI  4800000
#define EPS_F 1e-12f

#define CHUNK    1024
#define NCH_UI   ((NUI + CHUNK - 1) / CHUNK)   // 147
#define NCH_II   ((I_N + CHUNK - 1) / CHUNK)   // 49
#define NCH_TOT  (NCH_UI + NCH_II)             // 196

// ---------------- static device scratch (allocation-free) ----------------
__device__ int2  g_ui_csr[E_UI];       // packed (src, weight-bits)
__device__ int2  g_ii_csr[E_II];
__device__ int   g_ui_off[NUI + 1];
__device__ int   g_ui_cur[NUI];
__device__ int   g_ii_off[I_N + 1];
__device__ int   g_ii_cur[I_N];
__device__ int   g_chunksum[NCH_TOT];
__device__ int   g_chunkoff[NCH_TOT];

// fp16 propagation buffers; float4-typed for 16B alignment. Row = 128B = 8 float4.
__device__ float4 g_eh0[NUI * 8];
__device__ float4 g_eh1[NUI * 8];
__device__ float4 g_gh0[I_N * 8];
__device__ float4 g_gh1[I_N * 8];

// ---------------- CSR build ----------------
__global__ void k_zero() {
    int stride = gridDim.x * blockDim.x;
    for (int i = blockIdx.x * blockDim.x + threadIdx.x; i < NUI; i += stride) {
        g_ui_cur[i] = 0;
        if (i < I_N) g_ii_cur[i] = 0;
    }
}

__global__ void k_count(const int* __restrict__ ui_dst, const int* __restrict__ ii_dst) {
    int stride = gridDim.x * blockDim.x;
    for (int e = blockIdx.x * blockDim.x + threadIdx.x; e < E_UI; e += stride) {
        atomicAdd(&g_ui_cur[__ldcs(&ui_dst[e])], 1);
        if (e < E_II) atomicAdd(&g_ii_cur[__ldcs(&ii_dst[e])], 1);
    }
}

__global__ void __launch_bounds__(256) k_scan_partial() {
    int b = blockIdx.x;
    const int* deg;
    int base, n;
    if (b < NCH_UI) { deg = g_ui_cur; base = b * CHUNK; n = NUI; }
    else            { deg = g_ii_cur; base = (b - NCH_UI) * CHUNK; n = I_N; }

    int t = threadIdx.x;
    int i0 = base + t * 4;
    int s = 0;
    #pragma unroll
    for (int k = 0; k < 4; k++) {
        int i = i0 + k;
        if (i < n) s += deg[i];
    }
    #pragma unroll
    for (int o = 16; o; o >>= 1) s += __shfl_xor_sync(0xffffffffu, s, o);
    __shared__ int wsum[8];
    int lane = t & 31, wid = t >> 5;
    if (lane == 0) wsum[wid] = s;
    __syncthreads();
    if (t == 0) {
        int tot = 0;
        #pragma unroll
        for (int w = 0; w < 8; w++) tot += wsum[w];
        g_chunksum[b] = tot;
    }
}

__global__ void k_scan_chunks() {
    __shared__ int sh[NCH_TOT];
    int t = threadIdx.x;
    if (t < NCH_TOT) sh[t] = g_chunksum[t];
    __syncthreads();
    if (t == 0) {
        int run = 0;
        for (int c = 0; c < NCH_UI; c++) { int v = sh[c]; sh[c] = run; run += v; }
        run = 0;
        for (int c = NCH_UI; c < NCH_TOT; c++) { int v = sh[c]; sh[c] = run; run += v; }
        g_ui_off[NUI] = E_UI;
        g_ii_off[I_N] = E_II;
    }
    __syncthreads();
    if (t < NCH_TOT) g_chunkoff[t] = sh[t];
}

__global__ void __launch_bounds__(256) k_scan_final() {
    int b = blockIdx.x;
    int* deg; int* off;
    int base, n;
    if (b < NCH_UI) { deg = g_ui_cur; off = g_ui_off; base = b * CHUNK; n = NUI; }
    else            { deg = g_ii_cur; off = g_ii_off; base = (b - NCH_UI) * CHUNK; n = I_N; }
    int coff = g_chunkoff[b];

    int t = threadIdx.x;
    int lane = t & 31, wid = t >> 5;
    int i0 = base + t * 4;
    int v[4];
    int s = 0;
    #pragma unroll
    for (int k = 0; k < 4; k++) {
        int i = i0 + k;
        v[k] = (i < n) ? deg[i] : 0;
        s += v[k];
    }
    int x = s;
    #pragma unroll
    for (int o = 1; o < 32; o <<= 1) {
        int tmp = __shfl_up_sync(0xffffffffu, x, o);
        if (lane >= o) x += tmp;
    }
    __shared__ int wsum[8];
    if (lane == 31) wsum[wid] = x;
    __syncthreads();
    __shared__ int wexc[8];
    if (t == 0) {
        int run = 0;
        #pragma unroll
        for (int w = 0; w < 8; w++) { int tv = wsum[w]; wexc[w] = run; run += tv; }
    }
    __syncthreads();
    int running = coff + (x - s) + wexc[wid];
    #pragma unroll
    for (int k = 0; k < 4; k++) {
        int i = i0 + k;
        if (i < n) { off[i] = running; deg[i] = running; }
        running += v[k];
    }
}

__global__ void k_fill(const int* __restrict__ ui_src, const int* __restrict__ ui_dst,
                       const float* __restrict__ ui_w,
                       const int* __restrict__ ii_src, const int* __restrict__ ii_dst,
                       const float* __restrict__ ii_w) {
    int stride = gridDim.x * blockDim.x;
    for (int e = blockIdx.x * blockDim.x + threadIdx.x; e < E_UI; e += stride) {
        int d = __ldcs(&ui_dst[e]);
        int p = atomicAdd(&g_ui_cur[d], 1);
        g_ui_csr[p] = make_int2(__ldcs(&ui_src[e]), __float_as_int(__ldcs(&ui_w[e])));
        if (e < E_II) {
            int d2 = __ldcs(&ii_dst[e]);
            int p2 = atomicAdd(&g_ii_cur[d2], 1);
            g_ii_csr[p2] = make_int2(__ldcs(&ii_src[e]), __float_as_int(__ldcs(&ii_w[e])));
        }
    }
}

// ---------------- init: eh0 = fp16(ego), gh0 = fp16(Gis) ----------------
__global__ void k_init(const float* __restrict__ Gu, const float* __restrict__ Gi,
                       const float* __restrict__ Gis) {
    const int n1  = NUI * 32;
    const int nGu = U_N * 32;
    const int tot = n1 + I_N * 32;
    __half2* eh0 = (__half2*)g_eh0;
    __half2* gh0 = (__half2*)g_gh0;
    int stride = gridDim.x * blockDim.x;
    for (int i = blockIdx.x * blockDim.x + threadIdx.x; i < tot; i += stride) {
        if (i < n1) {
            float2 v = (i < nGu) ? __ldcs(&((const float2*)Gu)[i])
                                 : __ldcs(&((const float2*)Gi)[i - nGu]);
            eh0[i] = __float22half2_rn(v);
        } else {
            float2 v = __ldcs(&((const float2*)Gis)[i - n1]);
            gh0[i - n1] = __float22half2_rn(v);
        }
    }
}

// ---------------- gather core: 4 edge-slots x 8 lanes, 16-edge pipeline -----
__device__ __forceinline__ void gather_row(const int* __restrict__ off,
                                           const int2* __restrict__ csr,
                                           const float4* __restrict__ x,
                                           int row, int slot, int sub,
                                           float a[8]) {
    int beg = off[row], end = off[row + 1];
    #pragma unroll
    for (int k = 0; k < 8; k++) a[k] = 0.f;

    int2 ed[4];
    #pragma unroll
    for (int g = 0; g < 4; g++) {
        int i = beg + 4 * g + slot;
        ed[g] = (i < end) ? __ldg(&csr[i]) : make_int2(0, 0);
    }

    int e = beg;
    for (; e + 16 <= end; e += 16) {
        int2 nx[4];
        #pragma unroll
        for (int g = 0; g < 4; g++) {
            int i = e + 16 + 4 * g + slot;
            nx[g] = (i < end) ? __ldg(&csr[i]) : make_int2(0, 0);
        }
        float4 r[4];
        #pragma unroll
        for (int g = 0; g < 4; g++)
            r[g] = __ldg(&x[(size_t)ed[g].x * 8 + sub]);
        #pragma unroll
        for (int g = 0; g < 4; g++) {
            float w = __int_as_float(ed[g].y);
            const __half2* h = (const __half2*)&r[g];
            #pragma unroll
            for (int k = 0; k < 4; k++) {
                float2 f = __half22float2(h[k]);
                a[2 * k]     = fmaf(w, f.x, a[2 * k]);
                a[2 * k + 1] = fmaf(w, f.y, a[2 * k + 1]);
            }
        }
        #pragma unroll
        for (int g = 0; g < 4; g++) ed[g] = nx[g];
    }

    // tail: up to 16 edges already in ed[0..3] (zero-padded within groups)
    #pragma unroll
    for (int g = 0; g < 4; g++) {
        if (e + 4 * g < end) {
            float4 r = __ldg(&x[(size_t)ed[g].x * 8 + sub]);
            float w = __int_as_float(ed[g].y);
            const __half2* h = (const __half2*)&r;
            #pragma unroll
            for (int k = 0; k < 4; k++) {
                float2 f = __half22float2(h[k]);
                a[2 * k]     = fmaf(w, f.x, a[2 * k]);
                a[2 * k + 1] = fmaf(w, f.y, a[2 * k + 1]);
            }
        }
    }

    // cross-slot reduce -> all 4 slots hold identical column sums
    #pragma unroll
    for (int k = 0; k < 8; k++) {
        a[k] += __shfl_xor_sync(0xffffffffu, a[k], 8);
        a[k] += __shfl_xor_sync(0xffffffffu, a[k], 16);
    }
}

// ---------------- fused SpMM (round-5 structure) ----------------
// FIRST: acc-write = ego(Gu/Gi) + a    (layer 1)
// FINAL: acc = (acc + a)/4, item rows += l2norm(gh0)   (layer 3 + epilogue)
template <bool NORM, bool ACC, bool WX, bool FIRST, bool FINAL>
__global__ void __launch_bounds__(256) k_spmm(int gsel, int xsel, int ysel,
                                              float* acc,
                                              const float* __restrict__ Gu,
                                              const float* __restrict__ Gi,
                                              int nrows) {
    int row = blockIdx.x * 8 + (threadIdx.x >> 5);
    if (row >= nrows) return;
    int lane = threadIdx.x & 31;
    int slot = lane >> 3;
    int sub  = lane & 7;

    const int*  off = gsel ? g_ii_off : g_ui_off;
    const int2* csr = gsel ? g_ii_csr : g_ui_csr;
    const float4* x = (xsel == 0) ? g_eh0 : (xsel == 1) ? g_eh1
                    : (xsel == 2) ? g_gh0 : g_gh1;
    float4* y = (ysel == 0) ? g_eh0 : (ysel == 1) ? g_eh1
              : (ysel == 2) ? g_gh0 : g_gh1;

    float a[8];
    gather_row(off, csr, x, row, slot, sub, a);

    if (NORM) {
        float ssum = 0.f;
        #pragma unroll
        for (int k = 0; k < 8; k++) ssum = fmaf(a[k], a[k], ssum);
        #pragma unroll
        for (int o = 4; o; o >>= 1) ssum += __shfl_xor_sync(0xffffffffu, ssum, o);
        float scale = 1.f / fmaxf(sqrtf(ssum), EPS_F);
        #pragma unroll
        for (int k = 0; k < 8; k++) a[k] *= scale;
    }

    if (WX && slot == 0) {
        __half2 hp[4];
        #pragma unroll
        for (int k = 0; k < 4; k++)
            hp[k] = __float22half2_rn(make_float2(a[2 * k], a[2 * k + 1]));
        y[(size_t)row * 8 + sub] = *(const float4*)hp;
    }

    if ((ACC || FINAL) && slot < 2) {
        float4* a4 = (float4*)acc;
        size_t p = (size_t)row * 16 + 2 * sub + slot;
        float4 o;
        if (FIRST) {
            o = (row < U_N) ? ((const float4*)Gu)[p]
                            : ((const float4*)Gi)[(size_t)(row - U_N) * 16 + 2 * sub + slot];
        } else {
            o = a4[p];
        }
        o.x += a[4 * slot + 0];
        o.y += a[4 * slot + 1];
        o.z += a[4 * slot + 2];
        o.w += a[4 * slot + 3];
        if (FINAL) {
            o.x *= 0.25f; o.y *= 0.25f; o.z *= 0.25f; o.w *= 0.25f;
            if (row >= U_N) {
                float2 gp = ((const float2*)g_gh0)[(size_t)(row - U_N) * 16 + 2 * sub + slot];
                const __half2* gh = (const __half2*)&gp;
                float2 f0 = __half22float2(gh[0]);
                float2 f1 = __half22float2(gh[1]);
                float ssum = f0.x * f0.x + f0.y * f0.y + f1.x * f1.x + f1.y * f1.y;
                #pragma unroll
                for (int o2 = 8; o2; o2 >>= 1)
                    ssum += __shfl_xor_sync(0xffffffffu, ssum, o2);
                float sc = 1.f / fmaxf(sqrtf(ssum), EPS_F);
                o.x = fmaf(f0.x, sc, o.x);
                o.y = fmaf(f0.y, sc, o.y);
                o.z = fmaf(f1.x, sc, o.z);
                o.w = fmaf(f1.y, sc, o.w);
            }
        }
        a4[p] = o;
    }
}

// ---------------- launch ----------------
extern "C" void kernel_launch(void* const* d_in, const int* in_sizes, int n_in,
                              void* d_out, int out_size) {
    const float* Gu     = (const float*)d_in[0];
    const float* Gi     = (const float*)d_in[1];
    const float* Gis    = (const float*)d_in[2];
    const float* ii_w   = (const float*)d_in[3];
    const float* ui_w   = (const float*)d_in[4];
    const int*   ii_src = (const int*)d_in[5];
    const int*   ii_dst = (const int*)d_in[6];
    const int*   ui_src = (const int*)d_in[7];
    const int*   ui_dst = (const int*)d_in[8];
    float* out = (float*)d_out;

    // CSR build
    k_zero<<<512, 256>>>();
    k_count<<<4096, 256>>>(ui_dst, ii_dst);
    k_scan_partial<<<NCH_TOT, 256>>>();
    k_scan_chunks<<<1, 256>>>();
    k_scan_final<<<NCH_TOT, 256>>>();
    k_fill<<<4096, 256>>>(ui_src, ui_dst, ui_w, ii_src, ii_dst, ii_w);

    // fp16 copies of ego / Gis
    k_init<<<2048, 256>>>(Gu, Gi, Gis);

    int blk_ii = (I_N + 7) / 8;
    int blk_ui = (NUI + 7) / 8;

    // Item-item chain: gh1 = spmm(gh0); gh0 = spmm(gh1)
    k_spmm<false, false, true, false, false><<<blk_ii, 256>>>(1, 2, 3, nullptr, nullptr, nullptr, I_N);
    k_spmm<false, false, true, false, false><<<blk_ii, 256>>>(1, 3, 2, nullptr, nullptr, nullptr, I_N);

    // User-item chain:
    // L1: acc = ego + norm(spmm(eh0)); eh1 = fp16(norm)
    k_spmm<true, true, true, true, false><<<blk_ui, 256>>>(0, 0, 1, out, Gu, Gi, NUI);
    // L2: acc += norm(spmm(eh1)); eh0 = fp16(norm)
    k_spmm<true, true, true, false, false><<<blk_ui, 256>>>(0, 1, 0, out, nullptr, nullptr, NUI);
    // L3 + final: acc = (acc + norm(spmm(eh0)))/4 ; item rows += l2norm(gh0)
    k_spmm<true, false, false, false, true><<<blk_ui, 256>>>(0, 0, 1, out, nullptr, nullptr, NUI);
}